// round 5
// baseline (speedup 1.0000x reference)
#include <cuda_runtime.h>
#include <cuda_bf16.h>
#include <cstdint>

namespace {

constexpr int VJ = 25;    // joints
constexpr int TD = 300;   // time
constexpr int CD = 256;   // channels in/out
constexpr int NB = 32;    // batch
constexpr int BM = 256;   //全 C_out per block
constexpr int BN = 64;    // t-tile
constexpr int BK = 16;    // k-tile (input channels)

__device__ __forceinline__ void ffma2(unsigned long long& d, unsigned long long a, unsigned long long b) {
    asm("fma.rn.f32x2 %0, %1, %2, %0;" : "+l"(d) : "l"(a), "l"(b));
}
__device__ __forceinline__ unsigned long long splat2(float v) {
    unsigned long long r;
    asm("mov.b64 %0, {%1, %1};" : "=l"(r) : "f"(v));
    return r;
}
__device__ __forceinline__ void unpack2(unsigned long long v, float& lo, float& hi) {
    asm("mov.b64 {%0, %1}, %2;" : "=f"(lo), "=f"(hi) : "l"(v));
}

__global__ __launch_bounds__(256, 2)
void graphconv_kernel(const float* __restrict__ x, const float* __restrict__ A,
                      const float* __restrict__ W, const float* __restrict__ bias,
                      float* __restrict__ out)
{
    __shared__ __align__(16) float sW[BK][BM];   // sW[k][o] = W[o][kt+k]
    __shared__ __align__(16) float sB[BK][BN];   // sB[k][j] = agg[kt+k][tt+j]

    const int tt = blockIdx.x * BN;
    const int nz = blockIdx.z;
    const int n  = nz / VJ;
    const int w  = nz - n * VJ;

    // chain adjacency is tridiagonal: agg[.,w,.] = sum_{v in {w-1,w,w+1}} A[v][w] * x[.,v,.]
    const float a_self = A[w * VJ + w];
    const float a_prev = (w > 0)      ? A[(w - 1) * VJ + w] : 0.0f;
    const float a_next = (w < VJ - 1) ? A[(w + 1) * VJ + w] : 0.0f;

    const int tid = threadIdx.x;
    const int ty  = tid >> 4;       // 0..15 -> 16 output-channel rows each
    const int tx  = tid & 15;       // 0..15 -> 4 t-columns each
    const int kb  = ty;             // row of sB this thread loads
    const int j0  = tx * 4;

    const bool full = (tt + BN <= TD);

    unsigned long long acc[8][4];   // pairs along M (2 rows per u64), 4 cols
    #pragma unroll
    for (int r = 0; r < 8; ++r)
        #pragma unroll
        for (int j = 0; j < 4; ++j) acc[r][j] = 0ull;

    const float* xrow = x + (((size_t)n * CD) * VJ + (size_t)w) * TD;

    for (int kt = 0; kt < CD; kt += BK) {
        // ---- W tile: each thread loads 16 contiguous c for output row o = tid (64B/lane, coalesced)
        {
            const float4* wp = reinterpret_cast<const float4*>(W + (size_t)tid * CD + kt);
            float4 w0 = wp[0], w1 = wp[1], w2 = wp[2], w3 = wp[3];
            sW[ 0][tid] = w0.x; sW[ 1][tid] = w0.y; sW[ 2][tid] = w0.z; sW[ 3][tid] = w0.w;
            sW[ 4][tid] = w1.x; sW[ 5][tid] = w1.y; sW[ 6][tid] = w1.z; sW[ 7][tid] = w1.w;
            sW[ 8][tid] = w2.x; sW[ 9][tid] = w2.y; sW[10][tid] = w2.z; sW[11][tid] = w2.w;
            sW[12][tid] = w3.x; sW[13][tid] = w3.y; sW[14][tid] = w3.z; sW[15][tid] = w3.w;
        }
        // ---- agg tile: fused 3-tap stencil along V, vectorized along t
        {
            const int c = kt + kb;
            const float* p = xrow + (size_t)c * (VJ * TD) + tt + j0;
            if (full) {
                float4 vs = *reinterpret_cast<const float4*>(p);
                float4 r;
                r.x = a_self * vs.x; r.y = a_self * vs.y;
                r.z = a_self * vs.z; r.w = a_self * vs.w;
                if (w > 0) {
                    float4 vm = *reinterpret_cast<const float4*>(p - TD);
                    r.x += a_prev * vm.x; r.y += a_prev * vm.y;
                    r.z += a_prev * vm.z; r.w += a_prev * vm.w;
                }
                if (w < VJ - 1) {
                    float4 vp = *reinterpret_cast<const float4*>(p + TD);
                    r.x += a_next * vp.x; r.y += a_next * vp.y;
                    r.z += a_next * vp.z; r.w += a_next * vp.w;
                }
                *reinterpret_cast<float4*>(&sB[kb][j0]) = r;
            } else {
                #pragma unroll
                for (int jj = 0; jj < 4; ++jj) {
                    const int t = tt + j0 + jj;
                    float r = 0.0f;
                    if (t < TD) {
                        r = a_self * p[jj];
                        if (w > 0)      r += a_prev * p[jj - TD];
                        if (w < VJ - 1) r += a_next * p[jj + TD];
                    }
                    sB[kb][j0 + jj] = r;
                }
            }
        }
        __syncthreads();

        #pragma unroll
        for (int k = 0; k < BK; ++k) {
            // a-fragment: 16 consecutive W rows -> 8 natural f32x2 pairs (no repacking)
            unsigned long long a[8];
            const ulonglong2* ap = reinterpret_cast<const ulonglong2*>(&sW[k][ty * 16]);
            ulonglong2 a0 = ap[0], a1 = ap[1], a2 = ap[2], a3 = ap[3];
            a[0] = a0.x; a[1] = a0.y; a[2] = a1.x; a[3] = a1.y;
            a[4] = a2.x; a[5] = a2.y; a[6] = a3.x; a[7] = a3.y;
            // b-fragment: 4 t-columns, splatted into both halves
            float4 bv = *reinterpret_cast<const float4*>(&sB[k][j0]);
            unsigned long long b0 = splat2(bv.x), b1 = splat2(bv.y);
            unsigned long long b2 = splat2(bv.z), b3 = splat2(bv.w);
            #pragma unroll
            for (int r = 0; r < 8; ++r) {
                ffma2(acc[r][0], a[r], b0);
                ffma2(acc[r][1], a[r], b1);
                ffma2(acc[r][2], a[r], b2);
                ffma2(acc[r][3], a[r], b3);
            }
        }
        __syncthreads();
    }

    // ---- epilogue: unpack pairs, add bias, store (vectorized on interior tiles)
    const size_t obase = (((size_t)n * CD) * VJ + (size_t)w) * TD + tt + j0;
    #pragma unroll
    for (int r = 0; r < 8; ++r) {
        const int o0 = ty * 16 + 2 * r;
        float lo0, hi0, lo1, hi1, lo2, hi2, lo3, hi3;
        unpack2(acc[r][0], lo0, hi0);
        unpack2(acc[r][1], lo1, hi1);
        unpack2(acc[r][2], lo2, hi2);
        unpack2(acc[r][3], lo3, hi3);
        const float bl = bias[o0];
        const float bh = bias[o0 + 1];
        float4 rl = make_float4(lo0 + bl, lo1 + bl, lo2 + bl, lo3 + bl);
        float4 rh = make_float4(hi0 + bh, hi1 + bh, hi2 + bh, hi3 + bh);
        float* pl = out + obase + (size_t)o0 * (VJ * TD);
        float* ph = pl + (size_t)(VJ * TD);
        if (full) {
            *reinterpret_cast<float4*>(pl) = rl;
            *reinterpret_cast<float4*>(ph) = rh;
        } else {
            const float vl[4] = {rl.x, rl.y, rl.z, rl.w};
            const float vh[4] = {rh.x, rh.y, rh.z, rh.w};
            #pragma unroll
            for (int jj = 0; jj < 4; ++jj) {
                if (tt + j0 + jj < TD) { pl[jj] = vl[jj]; ph[jj] = vh[jj]; }
            }
        }
    }
}

} // namespace

extern "C" void kernel_launch(void* const* d_in, const int* in_sizes, int n_in,
                              void* d_out, int out_size) {
    const float* x    = (const float*)d_in[0];
    const float* A    = (const float*)d_in[1];
    const float* W    = (const float*)d_in[2];
    const float* b    = (const float*)d_in[3];
    float*       outp = (float*)d_out;

    dim3 grid((TD + BN - 1) / BN, 1, NB * VJ);   // 5 t-tiles x 800 (n,w) pairs
    graphconv_kernel<<<grid, 256>>>(x, A, W, b, outp);
}

// round 8
// speedup vs baseline: 1.2259x; 1.2259x over previous
#include <cuda_runtime.h>
#include <cuda_bf16.h>
#include <cstdint>

namespace {

constexpr int VJ = 25, TD = 300, CD = 256, NB = 32;
constexpr int BM = 128;      // output-channel rows per CTA
constexpr int BN = 64;       // t-columns per CTA
constexpr int BK = 64;       // input channels per smem chunk
constexpr int THREADS = 256; // 8 warps: 4 (m) x 2 (n)

constexpr int A_STRIDE = 144;               // 64 bf16 = 128B + 16B pad -> conflict-free LDSM
constexpr int SZ_A = BM * A_STRIDE;         // 18432 per (hi|lo)
constexpr int SZ_B = BK * 128;              // 8192  per (hi|lo)
constexpr int OFF_AH = 0;
constexpr int OFF_AL = SZ_A;
constexpr int OFF_BH = 2 * SZ_A;
constexpr int OFF_BL = 2 * SZ_A + SZ_B;
constexpr int SMEM_DYN = 2 * SZ_A + 2 * SZ_B;   // 53248 B

__device__ __forceinline__ uint32_t smem_u32(const void* p) {
    uint32_t a;
    asm("{ .reg .u64 t; cvta.to.shared.u64 t, %1; cvt.u32.u64 %0, t; }" : "=r"(a) : "l"(p));
    return a;
}

// pack two floats -> bf16x2 (x low half, y high half)
__device__ __forceinline__ uint32_t bfpack(float x, float y) {
    uint32_t r;
    asm("cvt.rn.bf16x2.f32 %0, %1, %2;" : "=r"(r) : "f"(y), "f"(x));
    return r;
}
__device__ __forceinline__ float resid(float a) {
    return a - __bfloat162float(__float2bfloat16(a));
}

__device__ __forceinline__ void ldsm_x4(uint32_t* r, uint32_t addr) {
    asm volatile("ldmatrix.sync.aligned.m8n8.x4.shared.b16 {%0,%1,%2,%3}, [%4];"
                 : "=r"(r[0]), "=r"(r[1]), "=r"(r[2]), "=r"(r[3]) : "r"(addr));
}
__device__ __forceinline__ void ldsm_x4_t(uint32_t* r, uint32_t addr) {
    asm volatile("ldmatrix.sync.aligned.m8n8.x4.trans.shared.b16 {%0,%1,%2,%3}, [%4];"
                 : "=r"(r[0]), "=r"(r[1]), "=r"(r[2]), "=r"(r[3]) : "r"(addr));
}
__device__ __forceinline__ void mma16816(float* c, const uint32_t* a, uint32_t b0, uint32_t b1) {
    asm volatile(
        "mma.sync.aligned.m16n8k16.row.col.f32.bf16.bf16.f32 "
        "{%0,%1,%2,%3}, {%4,%5,%6,%7}, {%8,%9}, {%0,%1,%2,%3};"
        : "+f"(c[0]), "+f"(c[1]), "+f"(c[2]), "+f"(c[3])
        : "r"(a[0]), "r"(a[1]), "r"(a[2]), "r"(a[3]), "r"(b0), "r"(b1));
}

// split fp32x4 -> bf16 hi/lo, store 8B into each tile at byte_off (multiple of 8)
__device__ __forceinline__ void split_store4(char* smem, int off_hi, int off_lo,
                                             uint32_t byte_off, float4 v) {
    uint2 h, l;
    h.x = bfpack(v.x, v.y);  h.y = bfpack(v.z, v.w);
    l.x = bfpack(resid(v.x), resid(v.y));
    l.y = bfpack(resid(v.z), resid(v.w));
    *reinterpret_cast<uint2*>(smem + off_hi + byte_off) = h;
    *reinterpret_cast<uint2*>(smem + off_lo + byte_off) = l;
}

__global__ __launch_bounds__(THREADS, 2)
void graphconv_mma_kernel(const float* __restrict__ x, const float* __restrict__ A,
                          const float* __restrict__ W, const float* __restrict__ bias,
                          float* __restrict__ out)
{
    extern __shared__ char smem[];
    const uint32_t sb = smem_u32(smem);

    const int tid  = threadIdx.x;
    const int lane = tid & 31;
    const int wid  = tid >> 5;
    const int warp_m = wid & 3;   // 0..3 -> 32 rows each
    const int warp_n = wid >> 2;  // 0..1 -> 32 cols each

    const int bx   = blockIdx.x;  // 0..9
    const int m    = bx & 1;      // M-half
    const int tcol = bx >> 1;     // 0..4
    const int w    = blockIdx.y;
    const int n    = blockIdx.z;
    const int t0   = tcol * BN;
    const bool full = (t0 + BN <= TD);

    const float a_self = A[w * VJ + w];
    const float a_prev = (w > 0)      ? A[(w - 1) * VJ + w] : 0.0f;
    const float a_next = (w < VJ - 1) ? A[(w + 1) * VJ + w] : 0.0f;

    float acc[2][4][4];
    #pragma unroll
    for (int i = 0; i < 2; ++i)
        #pragma unroll
        for (int j = 0; j < 4; ++j)
            #pragma unroll
            for (int e = 0; e < 4; ++e) acc[i][j][e] = 0.0f;

    // ---- ldmatrix address precompute (bytes, relative to tile base)
    // A (m16k16, x4): lanes 0-7 -> rows m0+0..7 (k0..7), 8-15 -> rows +8,
    //                 16-23 -> rows m0+0..7 (k8..15), 24-31 -> rows +8 (k8..15)
    uint32_t a_rowoff[2];
    {
        const int rbase = warp_m * 32 + (lane & 7) + ((lane >> 3) & 1) * 8;
        const int cbyte = (lane >> 4) * 16;            // k sub-block (8 bf16 = 16B)
        a_rowoff[0] = (uint32_t)(rbase * A_STRIDE + cbyte);
        a_rowoff[1] = (uint32_t)((rbase + 16) * A_STRIDE + cbyte);
    }
    // B (k16n16 per x4.trans): lanes 0-7 -> k0..7 @ n0, 8-15 -> k8..15 @ n0,
    //                          16-23 -> k0..7 @ n0+8, 24-31 -> k8..15 @ n0+8
    uint32_t b_off[2];
    {
        const int krow = (lane & 7) + ((lane >> 3) & 1) * 8;
        #pragma unroll
        for (int nb = 0; nb < 2; ++nb) {
            const int ncol = warp_n * 32 + nb * 16 + ((lane >> 4) & 1) * 8;
            b_off[nb] = (uint32_t)((krow * 128 + ncol * 2) ^ ((lane & 7) << 4));
        }
    }

    for (int kc = 0; kc < 4; ++kc) {
        const int c0 = kc * BK;

        // ---- A tile: W[m*128 + r][c0..c0+63] -> bf16 hi/lo (row-padded 144B)
        {
            const int r  = tid >> 1;
            const int q0 = (tid & 1) * 8;   // 8 float4 each
            const float4* wp =
                reinterpret_cast<const float4*>(W + (size_t)(m * BM + r) * CD + c0) + q0;
            #pragma unroll
            for (int q = 0; q < 8; ++q) {
                float4 v = wp[q];
                split_store4(smem, OFF_AH, OFF_AL,
                             (uint32_t)(r * A_STRIDE + (q0 + q) * 8), v);
            }
        }
        // ---- B tile: agg[c0+k][t0+j] via 3-tap stencil, XOR-swizzled 128B rows
        {
            const int kk = tid >> 2;        // 0..63
            const int q  = tid & 3;
            const int c  = c0 + kk;
            const float* ps = x + (((size_t)n * CD + c) * VJ + w) * TD + t0;
            #pragma unroll
            for (int qq = 0; qq < 4; ++qq) {
                const int j = q * 16 + qq * 4;
                float4 r4;
                if (full) {
                    float4 vs = *reinterpret_cast<const float4*>(ps + j);
                    r4.x = a_self * vs.x; r4.y = a_self * vs.y;
                    r4.z = a_self * vs.z; r4.w = a_self * vs.w;
                    if (w > 0) {
                        float4 vm = *reinterpret_cast<const float4*>(ps + j - TD);
                        r4.x += a_prev * vm.x; r4.y += a_prev * vm.y;
                        r4.z += a_prev * vm.z; r4.w += a_prev * vm.w;
                    }
                    if (w < VJ - 1) {
                        float4 vp = *reinterpret_cast<const float4*>(ps + j + TD);
                        r4.x += a_next * vp.x; r4.y += a_next * vp.y;
                        r4.z += a_next * vp.z; r4.w += a_next * vp.w;
                    }
                } else {
                    float tmp[4];
                    #pragma unroll
                    for (int e = 0; e < 4; ++e) {
                        float rv = 0.0f;
                        if (t0 + j + e < TD) {
                            rv = a_self * ps[j + e];
                            if (w > 0)      rv += a_prev * ps[j + e - TD];
                            if (w < VJ - 1) rv += a_next * ps[j + e + TD];
                        }
                        tmp[e] = rv;
                    }
                    r4 = make_float4(tmp[0], tmp[1], tmp[2], tmp[3]);
                }
                const uint32_t sw = (uint32_t)((kk * 128 + j * 2) ^ ((kk & 7) << 4));
                split_store4(smem, OFF_BH, OFF_BL, sw, r4);
            }
        }
        __syncthreads();

        // ---- 4 k16 steps: 8 ldmatrix.x4 + 24 mma per warp
        #pragma unroll
        for (int ks = 0; ks < 4; ++ks) {
            uint32_t ah[2][4], al[2][4], bh[2][4], bl[2][4];
            #pragma unroll
            for (int mt = 0; mt < 2; ++mt) {
                ldsm_x4(ah[mt], sb + OFF_AH + a_rowoff[mt] + ks * 32);
                ldsm_x4(al[mt], sb + OFF_AL + a_rowoff[mt] + ks * 32);
            }
            #pragma unroll
            for (int nb = 0; nb < 2; ++nb) {
                ldsm_x4_t(bh[nb], sb + OFF_BH + b_off[nb] + ks * 2048);
                ldsm_x4_t(bl[nb], sb + OFF_BL + b_off[nb] + ks * 2048);
            }
            #pragma unroll
            for (int mt = 0; mt < 2; ++mt) {
                #pragma unroll
                for (int nt = 0; nt < 4; ++nt) {
                    const int nb = nt >> 1, sel = (nt & 1) * 2;
                    mma16816(acc[mt][nt], ah[mt], bh[nb][sel], bh[nb][sel + 1]);
                    mma16816(acc[mt][nt], ah[mt], bl[nb][sel], bl[nb][sel + 1]);
                    mma16816(acc[mt][nt], al[mt], bh[nb][sel], bh[nb][sel + 1]);
                }
            }
        }
        __syncthreads();
    }

    // ---- epilogue: fragment layout c0=(g,2tg) c1=(g,2tg+1) c2=(g+8,2tg) c3=(g+8,2tg+1)
    const int g  = lane >> 2;
    const int tg = lane & 3;
    #pragma unroll
    for (int mt = 0; mt < 2; ++mt) {
        const int o0 = m * BM + warp_m * 32 + mt * 16 + g;
        const float bv0 = bias[o0];
        const float bv1 = bias[o0 + 8];
        float* row0 = out + (((size_t)n * CD + o0    ) * VJ + w) * TD;
        float* row1 = out + (((size_t)n * CD + o0 + 8) * VJ + w) * TD;
        #pragma unroll
        for (int nt = 0; nt < 4; ++nt) {
            const int t = t0 + warp_n * 32 + nt * 8 + 2 * tg;   // always even; TD even
            if (t < TD) {
                float2 v0 = make_float2(acc[mt][nt][0] + bv0, acc[mt][nt][1] + bv0);
                float2 v1 = make_float2(acc[mt][nt][2] + bv1, acc[mt][nt][3] + bv1);
                *reinterpret_cast<float2*>(row0 + t) = v0;
                *reinterpret_cast<float2*>(row1 + t) = v1;
            }
        }
    }
}

} // namespace

extern "C" void kernel_launch(void* const* d_in, const int* in_sizes, int n_in,
                              void* d_out, int out_size) {
    const float* x    = (const float*)d_in[0];
    const float* A    = (const float*)d_in[1];
    const float* W    = (const float*)d_in[2];
    const float* b    = (const float*)d_in[3];
    float*       outp = (float*)d_out;

    cudaFuncSetAttribute(graphconv_mma_kernel,
                         cudaFuncAttributeMaxDynamicSharedMemorySize, SMEM_DYN);

    dim3 grid(10, VJ, NB);   // (m,tcol) x w x n = 8000 CTAs
    graphconv_mma_kernel<<<grid, THREADS, SMEM_DYN>>>(x, A, W, b, outp);
}

// round 9
// speedup vs baseline: 1.6101x; 1.3134x over previous
#include <cuda_runtime.h>
#include <cuda_bf16.h>
#include <cstdint>

namespace {

constexpr int VJ = 25, TD = 300, CD = 256, NB = 32;
constexpr int NF   = VJ * TD;     // 7500 flattened (w,t)
constexpr int ASTR = 7504;        // padded agg row stride (16B-aligned rows)
constexpr int BM = 128, BN = 128, BK = 64;
constexpr int THREADS = 256;

// smem: A hi | A lo | B hi | B lo  (16 KB each)
constexpr int OFF_AH = 0;
constexpr int OFF_AL = 16384;
constexpr int OFF_BH = 32768;
constexpr int OFF_BL = 49152;
constexpr int SMEM_DYN = 65536;

// persistent scratch (allocation-free workaround)
__device__ __nv_bfloat16 g_aggh[(size_t)NB * CD * ASTR + 128];
__device__ __nv_bfloat16 g_aggl[(size_t)NB * CD * ASTR + 128];
__device__ __nv_bfloat16 g_wh[CD * CD];
__device__ __nv_bfloat16 g_wl[CD * CD];

__device__ __forceinline__ uint32_t smem_u32(const void* p) {
    uint32_t a;
    asm("{ .reg .u64 t; cvta.to.shared.u64 t, %1; cvt.u32.u64 %0, t; }" : "=r"(a) : "l"(p));
    return a;
}
// pack two floats -> bf16x2 (x low half, y high half)
__device__ __forceinline__ uint32_t bfpack(float x, float y) {
    uint32_t r;
    asm("cvt.rn.bf16x2.f32 %0, %1, %2;" : "=r"(r) : "f"(y), "f"(x));
    return r;
}
__device__ __forceinline__ float resid(float a) {
    return a - __bfloat162float(__float2bfloat16(a));
}
__device__ __forceinline__ void cpa16(uint32_t dst, const void* src) {
    asm volatile("cp.async.ca.shared.global [%0], [%1], 16;" :: "r"(dst), "l"(src));
}
__device__ __forceinline__ void ldsm_x4(uint32_t* r, uint32_t addr) {
    asm volatile("ldmatrix.sync.aligned.m8n8.x4.shared.b16 {%0,%1,%2,%3}, [%4];"
                 : "=r"(r[0]), "=r"(r[1]), "=r"(r[2]), "=r"(r[3]) : "r"(addr));
}
__device__ __forceinline__ void ldsm_x4_t(uint32_t* r, uint32_t addr) {
    asm volatile("ldmatrix.sync.aligned.m8n8.x4.trans.shared.b16 {%0,%1,%2,%3}, [%4];"
                 : "=r"(r[0]), "=r"(r[1]), "=r"(r[2]), "=r"(r[3]) : "r"(addr));
}
__device__ __forceinline__ void mma16816(float* c, const uint32_t* a, uint32_t b0, uint32_t b1) {
    asm volatile(
        "mma.sync.aligned.m16n8k16.row.col.f32.bf16.bf16.f32 "
        "{%0,%1,%2,%3}, {%4,%5,%6,%7}, {%8,%9}, {%0,%1,%2,%3};"
        : "+f"(c[0]), "+f"(c[1]), "+f"(c[2]), "+f"(c[3])
        : "r"(a[0]), "r"(a[1]), "r"(a[2]), "r"(a[3]), "r"(b0), "r"(b1));
}

// ---- pre-pass: W fp32 -> bf16 hi/lo
__global__ void prep_w(const float* __restrict__ W) {
    const int i = blockIdx.x * 256 + threadIdx.x;   // 16384 float4s
    float4 v = reinterpret_cast<const float4*>(W)[i];
    uint2 h, l;
    h.x = bfpack(v.x, v.y);            h.y = bfpack(v.z, v.w);
    l.x = bfpack(resid(v.x), resid(v.y)); l.y = bfpack(resid(v.z), resid(v.w));
    reinterpret_cast<uint2*>(g_wh)[i] = h;
    reinterpret_cast<uint2*>(g_wl)[i] = l;
}

// ---- pre-pass: agg = 3-tap stencil over joints, fp32 -> bf16 hi/lo (padded rows)
__global__ void prep_agg(const float* __restrict__ x, const float* __restrict__ A) {
    const int i  = blockIdx.x * 256 + threadIdx.x;  // 15,360,000 float4s exactly
    const int nc = i / 1875;                        // (n,c) row
    const int t4 = (i - nc * 1875) * 4;             // 0..7496, never crosses a w boundary
    const int w  = t4 / TD;
    const float* ps = x + (size_t)nc * NF + t4;
    const float a_s = A[w * VJ + w];
    float4 v = *reinterpret_cast<const float4*>(ps);
    float4 r;
    r.x = a_s * v.x; r.y = a_s * v.y; r.z = a_s * v.z; r.w = a_s * v.w;
    if (w > 0) {
        const float a_p = A[(w - 1) * VJ + w];
        float4 vm = *reinterpret_cast<const float4*>(ps - TD);
        r.x += a_p * vm.x; r.y += a_p * vm.y; r.z += a_p * vm.z; r.w += a_p * vm.w;
    }
    if (w < VJ - 1) {
        const float a_n = A[(w + 1) * VJ + w];
        float4 vp = *reinterpret_cast<const float4*>(ps + TD);
        r.x += a_n * vp.x; r.y += a_n * vp.y; r.z += a_n * vp.z; r.w += a_n * vp.w;
    }
    const size_t ob = (size_t)nc * ASTR + t4;
    uint2 h, l;
    h.x = bfpack(r.x, r.y);               h.y = bfpack(r.z, r.w);
    l.x = bfpack(resid(r.x), resid(r.y)); l.y = bfpack(resid(r.z), resid(r.w));
    *reinterpret_cast<uint2*>(g_aggh + ob) = h;
    *reinterpret_cast<uint2*>(g_aggl + ob) = l;
}

// ---- main GEMM: out[n] = W[256x256] @ agg[n][256 x 7500] (+bias), bf16 3-split
__global__ __launch_bounds__(THREADS, 3)
void gemm_kernel(const float* __restrict__ bias, float* __restrict__ out)
{
    extern __shared__ char smem[];
    const uint32_t sb = smem_u32(smem);

    const int tid  = threadIdx.x;
    const int lane = tid & 31;
    const int wid  = tid >> 5;
    const int warp_m = wid & 1;    // 2 warps -> 64 rows each
    const int warp_n = wid >> 1;   // 4 warps -> 32 cols each

    const int nt0 = blockIdx.x * BN;   // 0..7424
    const int m   = blockIdx.y;        // M-half
    const int n   = blockIdx.z;        // batch

    float acc[4][4][4];
    #pragma unroll
    for (int a = 0; a < 4; ++a)
        #pragma unroll
        for (int b = 0; b < 4; ++b)
            #pragma unroll
            for (int e = 0; e < 4; ++e) acc[a][b][e] = 0.0f;

    // ---- LDSM address precompute
    uint32_t a_base[4]; uint32_t a_x[4];
    #pragma unroll
    for (int mt = 0; mt < 4; ++mt) {
        const int r = warp_m * 64 + mt * 16 + (lane & 7) + ((lane >> 3) & 1) * 8;
        a_base[mt] = sb + (uint32_t)(r * 128);
        a_x[mt]    = (uint32_t)(r & 7);
    }
    const uint32_t a_c = (uint32_t)(lane >> 4);       // k sub-chunk 0/1
    const int krow = (lane & 7) + ((lane >> 3) & 1) * 8;
    uint32_t b_base[2];
    #pragma unroll
    for (int nb = 0; nb < 2; ++nb) {
        const int cchunk = warp_n * 4 + nb * 2 + (lane >> 4);
        b_base[nb] = sb + (uint32_t)(krow * 256 + ((cchunk ^ (krow & 7)) << 4));
    }

    for (int kc = 0; kc < 4; ++kc) {
        const int c0 = kc * BK;

        // A tiles: W bf16 hi/lo, rows of 128B, chunk swizzle c^(r&7)
        #pragma unroll
        for (int q = 0; q < 4; ++q) {
            const int idx = tid + q * 256;            // 0..1023
            const int r = idx >> 3, c = idx & 7;
            const uint32_t dst = sb + OFF_AH + (uint32_t)(r * 128 + ((c ^ (r & 7)) << 4));
            const size_t so = (size_t)(m * BM + r) * CD + c0 + c * 8;
            cpa16(dst, g_wh + so);
            cpa16(dst + (OFF_AL - OFF_AH), g_wl + so);
        }
        // B tiles: agg bf16 hi/lo, rows of 256B, chunk swizzle cc^(k&7)
        #pragma unroll
        for (int q = 0; q < 4; ++q) {
            const int idx = tid + q * 256;            // 0..1023
            const int k = idx >> 4, cc = idx & 15;
            const uint32_t dst = sb + OFF_BH + (uint32_t)(k * 256 + ((cc ^ (k & 7)) << 4));
            const size_t so = (size_t)(n * CD + c0 + k) * ASTR + nt0 + cc * 8;
            cpa16(dst, g_aggh + so);
            cpa16(dst + (OFF_BL - OFF_BH), g_aggl + so);
        }
        asm volatile("cp.async.commit_group;" ::: "memory");
        asm volatile("cp.async.wait_group 0;" ::: "memory");
        __syncthreads();

        #pragma unroll
        for (int ks = 0; ks < 4; ++ks) {
            uint32_t ah[4][4], al[4][4], bh[2][4], bl[2][4];
            #pragma unroll
            for (int mt = 0; mt < 4; ++mt) {
                const uint32_t ad = a_base[mt] + ((((uint32_t)(ks * 2) + a_c) ^ a_x[mt]) << 4);
                ldsm_x4(ah[mt], ad + OFF_AH);
                ldsm_x4(al[mt], ad + OFF_AL);
            }
            #pragma unroll
            for (int nb = 0; nb < 2; ++nb) {
                const uint32_t bd = b_base[nb] + (uint32_t)(ks * 4096);
                ldsm_x4_t(bh[nb], bd + OFF_BH);
                ldsm_x4_t(bl[nb], bd + OFF_BL);
            }
            #pragma unroll
            for (int mt = 0; mt < 4; ++mt) {
                #pragma unroll
                for (int nt = 0; nt < 4; ++nt) {
                    const int nb = nt >> 1, sel = (nt & 1) * 2;
                    mma16816(acc[mt][nt], ah[mt], bh[nb][sel], bh[nb][sel + 1]);
                    mma16816(acc[mt][nt], ah[mt], bl[nb][sel], bl[nb][sel + 1]);
                    mma16816(acc[mt][nt], al[mt], bh[nb][sel], bh[nb][sel + 1]);
                }
            }
        }
        __syncthreads();
    }

    // ---- epilogue: c0=(g,2tg) c1=(g,2tg+1) c2=(g+8,2tg) c3=(g+8,2tg+1)
    const int g  = lane >> 2;
    const int tg = lane & 3;
    #pragma unroll
    for (int mt = 0; mt < 4; ++mt) {
        const int o0 = m * BM + warp_m * 64 + mt * 16 + g;
        const float bv0 = bias[o0];
        const float bv1 = bias[o0 + 8];
        float* row0 = out + ((size_t)n * CD + o0    ) * NF;
        float* row1 = out + ((size_t)n * CD + o0 + 8) * NF;
        #pragma unroll
        for (int nt = 0; nt < 4; ++nt) {
            const int idx = nt0 + warp_n * 32 + nt * 8 + 2 * tg;   // even; NF even
            if (idx < NF) {
                float2 v0 = make_float2(acc[mt][nt][0] + bv0, acc[mt][nt][1] + bv0);
                float2 v1 = make_float2(acc[mt][nt][2] + bv1, acc[mt][nt][3] + bv1);
                *reinterpret_cast<float2*>(row0 + idx) = v0;
                *reinterpret_cast<float2*>(row1 + idx) = v1;
            }
        }
    }
}

} // namespace

extern "C" void kernel_launch(void* const* d_in, const int* in_sizes, int n_in,
                              void* d_out, int out_size) {
    const float* x    = (const float*)d_in[0];
    const float* A    = (const float*)d_in[1];
    const float* W    = (const float*)d_in[2];
    const float* b    = (const float*)d_in[3];
    float*       outp = (float*)d_out;

    prep_w<<<64, 256>>>(W);
    prep_agg<<<60000, 256>>>(x, A);

    cudaFuncSetAttribute(gemm_kernel,
                         cudaFuncAttributeMaxDynamicSharedMemorySize, SMEM_DYN);
    dim3 grid((NF + BN - 1) / BN, 2, NB);   // 59 x 2 x 32 = 3776 CTAs
    gemm_kernel<<<grid, THREADS, SMEM_DYN>>>(b, outp);
}

// round 10
// speedup vs baseline: 2.5805x; 1.6027x over previous
#include <cuda_runtime.h>
#include <cuda_bf16.h>
#include <cstdint>

namespace {

constexpr int VJ = 25, TD = 300, CD = 256, NB = 32;
constexpr int NF   = VJ * TD;     // 7500 flattened (w,t)
constexpr int ASTR = 7504;        // padded agg row stride (16B-aligned rows)
constexpr int BM = 128, BN = 128, BK = 32;
constexpr int NCHUNK = CD / BK;   // 8
constexpr int THREADS = 256;

// per-stage smem layout: A hi (128x80B) | A lo | B hi (32x256B) | B lo
constexpr int A_STRIDE = 80;                  // 64B data + 16B pad -> conflict-free LDSM
constexpr int OFF_AH = 0;
constexpr int OFF_AL = BM * A_STRIDE;         // 10240
constexpr int OFF_BH = 2 * BM * A_STRIDE;     // 20480
constexpr int OFF_BL = OFF_BH + BK * 256;     // 28672
constexpr int STAGE  = OFF_BL + BK * 256;     // 36864
constexpr int SMEM_DYN = 2 * STAGE;           // 73728

// persistent scratch (allocation-free workaround)
__device__ __nv_bfloat16 g_aggh[(size_t)NB * CD * ASTR + 128];
__device__ __nv_bfloat16 g_aggl[(size_t)NB * CD * ASTR + 128];
__device__ __nv_bfloat16 g_wh[CD * CD];
__device__ __nv_bfloat16 g_wl[CD * CD];

__device__ __forceinline__ uint32_t smem_u32(const void* p) {
    uint32_t a;
    asm("{ .reg .u64 t; cvta.to.shared.u64 t, %1; cvt.u32.u64 %0, t; }" : "=r"(a) : "l"(p));
    return a;
}
__device__ __forceinline__ uint32_t bfpack(float x, float y) {
    uint32_t r;
    asm("cvt.rn.bf16x2.f32 %0, %1, %2;" : "=r"(r) : "f"(y), "f"(x));
    return r;
}
__device__ __forceinline__ float resid(float a) {
    return a - __bfloat162float(__float2bfloat16(a));
}
__device__ __forceinline__ void cpa16(uint32_t dst, const void* src) {
    asm volatile("cp.async.ca.shared.global [%0], [%1], 16;" :: "r"(dst), "l"(src));
}
__device__ __forceinline__ void ldsm_x4(uint32_t* r, uint32_t addr) {
    asm volatile("ldmatrix.sync.aligned.m8n8.x4.shared.b16 {%0,%1,%2,%3}, [%4];"
                 : "=r"(r[0]), "=r"(r[1]), "=r"(r[2]), "=r"(r[3]) : "r"(addr));
}
__device__ __forceinline__ void ldsm_x4_t(uint32_t* r, uint32_t addr) {
    asm volatile("ldmatrix.sync.aligned.m8n8.x4.trans.shared.b16 {%0,%1,%2,%3}, [%4];"
                 : "=r"(r[0]), "=r"(r[1]), "=r"(r[2]), "=r"(r[3]) : "r"(addr));
}
__device__ __forceinline__ void mma16816(float* c, const uint32_t* a, uint32_t b0, uint32_t b1) {
    asm volatile(
        "mma.sync.aligned.m16n8k16.row.col.f32.bf16.bf16.f32 "
        "{%0,%1,%2,%3}, {%4,%5,%6,%7}, {%8,%9}, {%0,%1,%2,%3};"
        : "+f"(c[0]), "+f"(c[1]), "+f"(c[2]), "+f"(c[3])
        : "r"(a[0]), "r"(a[1]), "r"(a[2]), "r"(a[3]), "r"(b0), "r"(b1));
}

// ---- pre-pass: W fp32 -> bf16 hi/lo
__global__ void prep_w(const float* __restrict__ W) {
    const int i = blockIdx.x * 256 + threadIdx.x;   // 16384 float4s
    float4 v = reinterpret_cast<const float4*>(W)[i];
    uint2 h, l;
    h.x = bfpack(v.x, v.y);               h.y = bfpack(v.z, v.w);
    l.x = bfpack(resid(v.x), resid(v.y)); l.y = bfpack(resid(v.z), resid(v.w));
    reinterpret_cast<uint2*>(g_wh)[i] = h;
    reinterpret_cast<uint2*>(g_wl)[i] = l;
}

// ---- pre-pass: agg = 3-tap stencil over joints, fp32 -> bf16 hi/lo (padded rows)
__global__ void prep_agg(const float* __restrict__ x, const float* __restrict__ A) {
    const int i  = blockIdx.x * 256 + threadIdx.x;  // 15,360,000 float4s exactly
    const int nc = i / 1875;                        // (n,c) row
    const int t4 = (i - nc * 1875) * 4;             // never crosses a w boundary
    const int w  = t4 / TD;
    const float* ps = x + (size_t)nc * NF + t4;
    const float a_s = A[w * VJ + w];
    float4 v = *reinterpret_cast<const float4*>(ps);
    float4 r;
    r.x = a_s * v.x; r.y = a_s * v.y; r.z = a_s * v.z; r.w = a_s * v.w;
    if (w > 0) {
        const float a_p = A[(w - 1) * VJ + w];
        float4 vm = *reinterpret_cast<const float4*>(ps - TD);
        r.x += a_p * vm.x; r.y += a_p * vm.y; r.z += a_p * vm.z; r.w += a_p * vm.w;
    }
    if (w < VJ - 1) {
        const float a_n = A[(w + 1) * VJ + w];
        float4 vp = *reinterpret_cast<const float4*>(ps + TD);
        r.x += a_n * vp.x; r.y += a_n * vp.y; r.z += a_n * vp.z; r.w += a_n * vp.w;
    }
    const size_t ob = (size_t)nc * ASTR + t4;
    uint2 h, l;
    h.x = bfpack(r.x, r.y);               h.y = bfpack(r.z, r.w);
    l.x = bfpack(resid(r.x), resid(r.y)); l.y = bfpack(resid(r.z), resid(r.w));
    *reinterpret_cast<uint2*>(g_aggh + ob) = h;
    *reinterpret_cast<uint2*>(g_aggl + ob) = l;
}

// ---- main GEMM: out[n] = W[256x256] @ agg[n][256 x 7500] (+bias), bf16 3-split
__global__ __launch_bounds__(THREADS, 2)
void gemm_kernel(const float* __restrict__ bias, float* __restrict__ out)
{
    extern __shared__ char smem[];
    const uint32_t sb = smem_u32(smem);

    const int tid  = threadIdx.x;
    const int lane = tid & 31;
    const int wid  = tid >> 5;
    const int warp_m = wid & 1;    // 2 warps -> 64 rows each
    const int warp_n = wid >> 1;   // 4 warps -> 32 cols each

    const int nt0 = blockIdx.x * BN;
    const int m   = blockIdx.y;        // M-half
    const int n   = blockIdx.z;        // batch

    float acc[4][4][4];
    #pragma unroll
    for (int a = 0; a < 4; ++a)
        #pragma unroll
        for (int b = 0; b < 4; ++b)
            #pragma unroll
            for (int e = 0; e < 4; ++e) acc[a][b][e] = 0.0f;

    // ---- cp.async producer (one chunk into one stage)
    auto load_chunk = [&](int kc, int stg) {
        const int c0 = kc * BK;
        const uint32_t stb = sb + stg * STAGE;
        #pragma unroll
        for (int q = 0; q < 2; ++q) {               // A: 128 rows x 4 chunks, hi+lo
            const int idx = tid + q * 256;
            const int r = idx >> 2, c = idx & 3;
            const uint32_t dst = stb + OFF_AH + (uint32_t)(r * A_STRIDE + c * 16);
            const size_t so = (size_t)(m * BM + r) * CD + c0 + c * 8;
            cpa16(dst, g_wh + so);
            cpa16(dst + OFF_AL, g_wl + so);
        }
        #pragma unroll
        for (int q = 0; q < 2; ++q) {               // B: 32 k-rows x 16 chunks, hi+lo
            const int idx = tid + q * 256;
            const int k = idx >> 4, cc = idx & 15;
            const uint32_t dst = stb + OFF_BH + (uint32_t)(k * 256 + ((cc ^ (k & 7)) << 4));
            const size_t so = (size_t)(n * CD + c0 + k) * ASTR + nt0 + cc * 8;
            cpa16(dst, g_aggh + so);
            cpa16(dst + (OFF_BL - OFF_BH), g_aggl + so);
        }
        asm volatile("cp.async.commit_group;" ::: "memory");
    };

    // ---- LDSM address precompute
    uint32_t a_row[4];
    #pragma unroll
    for (int mt = 0; mt < 4; ++mt) {
        const int r = warp_m * 64 + mt * 16 + (lane & 7) + ((lane >> 3) & 1) * 8;
        a_row[mt] = (uint32_t)(r * A_STRIDE) + ((uint32_t)(lane >> 4) << 4);
    }
    const int krow = (lane & 7) + ((lane >> 3) & 1) * 8;
    uint32_t b_base[2];
    #pragma unroll
    for (int nb = 0; nb < 2; ++nb) {
        const int cchunk = warp_n * 4 + nb * 2 + (lane >> 4);
        b_base[nb] = (uint32_t)(krow * 256 + ((cchunk ^ (krow & 7)) << 4));
    }

    load_chunk(0, 0);

    for (int kc = 0; kc < NCHUNK; ++kc) {
        const int stg = kc & 1;
        if (kc + 1 < NCHUNK) {
            load_chunk(kc + 1, stg ^ 1);
            asm volatile("cp.async.wait_group 1;" ::: "memory");
        } else {
            asm volatile("cp.async.wait_group 0;" ::: "memory");
        }
        __syncthreads();

        const uint32_t stb = sb + stg * STAGE;
        #pragma unroll
        for (int ks = 0; ks < 2; ++ks) {
            uint32_t ah[4][4], al[4][4], bh[2][4], bl[2][4];
            #pragma unroll
            for (int mt = 0; mt < 4; ++mt) {
                const uint32_t ad = stb + a_row[mt] + (uint32_t)(ks * 32);
                ldsm_x4(ah[mt], ad + OFF_AH);
                ldsm_x4(al[mt], ad + OFF_AL);
            }
            #pragma unroll
            for (int nb = 0; nb < 2; ++nb) {
                const uint32_t bd = stb + b_base[nb] + (uint32_t)(ks * 4096);
                ldsm_x4_t(bh[nb], bd + OFF_BH);
                ldsm_x4_t(bl[nb], bd + OFF_BL);
            }
            #pragma unroll
            for (int mt = 0; mt < 4; ++mt) {
                #pragma unroll
                for (int nt = 0; nt < 4; ++nt) {
                    const int nb = nt >> 1, sel = (nt & 1) * 2;
                    mma16816(acc[mt][nt], ah[mt], bh[nb][sel], bh[nb][sel + 1]);
                    mma16816(acc[mt][nt], ah[mt], bl[nb][sel], bl[nb][sel + 1]);
                    mma16816(acc[mt][nt], al[mt], bh[nb][sel], bh[nb][sel + 1]);
                }
            }
        }
        __syncthreads();
    }

    // ---- epilogue: c0=(g,2tg) c1=(g,2tg+1) c2=(g+8,2tg) c3=(g+8,2tg+1)
    const int g  = lane >> 2;
    const int tg = lane & 3;
    #pragma unroll
    for (int mt = 0; mt < 4; ++mt) {
        const int o0 = m * BM + warp_m * 64 + mt * 16 + g;
        const float bv0 = bias[o0];
        const float bv1 = bias[o0 + 8];
        float* row0 = out + ((size_t)n * CD + o0    ) * NF;
        float* row1 = out + ((size_t)n * CD + o0 + 8) * NF;
        #pragma unroll
        for (int nt = 0; nt < 4; ++nt) {
            const int idx = nt0 + warp_n * 32 + nt * 8 + 2 * tg;   // even; NF even
            if (idx < NF) {
                float2 v0 = make_float2(acc[mt][nt][0] + bv0, acc[mt][nt][1] + bv0);
                float2 v1 = make_float2(acc[mt][nt][2] + bv1, acc[mt][nt][3] + bv1);
                *reinterpret_cast<float2*>(row0 + idx) = v0;
                *reinterpret_cast<float2*>(row1 + idx) = v1;
            }
        }
    }
}

} // namespace

extern "C" void kernel_launch(void* const* d_in, const int* in_sizes, int n_in,
                              void* d_out, int out_size) {
    const float* x    = (const float*)d_in[0];
    const float* A    = (const float*)d_in[1];
    const float* W    = (const float*)d_in[2];
    const float* b    = (const float*)d_in[3];
    float*       outp = (float*)d_out;

    prep_w<<<64, 256>>>(W);
    prep_agg<<<60000, 256>>>(x, A);

    cudaFuncSetAttribute(gemm_kernel,
                         cudaFuncAttributeMaxDynamicSharedMemorySize, SMEM_DYN);
    dim3 grid((NF + BN - 1) / BN, 2, NB);   // 59 x 2 x 32 = 3776 CTAs
    gemm_kernel<<<grid, THREADS, SMEM_DYN>>>(b, outp);
}

// round 11
// speedup vs baseline: 2.6659x; 1.0331x over previous
#include <cuda_runtime.h>
#include <cuda_bf16.h>
#include <cstdint>

namespace {

constexpr int VJ = 25, TD = 300, CD = 256, NB = 32;
constexpr int NF   = VJ * TD;     // 7500 flattened (w,t)
constexpr int ASTR = 7504;        // padded agg row stride (16B-aligned rows)
constexpr int BM = 128, BN = 128, BK = 32;
constexpr int NCHUNK = CD / BK;   // 8
constexpr int THREADS = 256;
constexpr int NSTAGE = 3;

// per-stage smem: A fragments (16 KB) | B rows 32 x 132 floats (16896 B)
constexpr int BROW  = 132;                    // floats per B row (128 + 4 pad)
constexpr int OFF_A = 0;
constexpr int OFF_B = 16384;
constexpr int STAGE = OFF_B + BK * BROW * 4;  // 33280
constexpr int SMEM_DYN = NSTAGE * STAGE;      // 99840

// persistent scratch (allocation-free workaround)
__device__ float g_aggt[(size_t)NB * CD * ASTR + 256];  // tf32-rounded agg
__device__ float g_wt[CD * CD];                          // W in fragment order, tf32-rounded

__device__ __forceinline__ uint32_t smem_u32(const void* p) {
    uint32_t a;
    asm("{ .reg .u64 t; cvta.to.shared.u64 t, %1; cvt.u32.u64 %0, t; }" : "=r"(a) : "l"(p));
    return a;
}
__device__ __forceinline__ float tf32r(float v) {
    float r;
    asm("cvt.rna.tf32.f32 %0, %1;" : "=f"(r) : "f"(v));
    return r;
}
__device__ __forceinline__ void cpa16(uint32_t dst, const void* src) {
    asm volatile("cp.async.ca.shared.global [%0], [%1], 16;" :: "r"(dst), "l"(src));
}
__device__ __forceinline__ void lds128(uint32_t* r, uint32_t addr) {
    asm volatile("ld.shared.v4.b32 {%0,%1,%2,%3}, [%4];"
                 : "=r"(r[0]), "=r"(r[1]), "=r"(r[2]), "=r"(r[3]) : "r"(addr));
}
__device__ __forceinline__ uint32_t lds32(uint32_t addr) {
    uint32_t r;
    asm volatile("ld.shared.b32 %0, [%1];" : "=r"(r) : "r"(addr));
    return r;
}
__device__ __forceinline__ void mma_tf32(float* c, const uint32_t* a, uint32_t b0, uint32_t b1) {
    asm volatile(
        "mma.sync.aligned.m16n8k8.row.col.f32.tf32.tf32.f32 "
        "{%0,%1,%2,%3}, {%4,%5,%6,%7}, {%8,%9}, {%0,%1,%2,%3};"
        : "+f"(c[0]), "+f"(c[1]), "+f"(c[2]), "+f"(c[3])
        : "r"(a[0]), "r"(a[1]), "r"(a[2]), "r"(a[3]), "r"(b0), "r"(b1));
}

// ---- pre-pass: W -> tf32-rounded, stored in m16n8k8 A-fragment order.
// blob index ((rblk*32 + cch)*32 + lane): 4 floats = a0..a3 of tile (rblk*16, cch*8)
__global__ void prep_w(const float* __restrict__ W) {
    const int i    = blockIdx.x * 256 + threadIdx.x;  // 0..16383
    const int lane = i & 31;
    const int cch  = (i >> 5) & 31;
    const int rblk = i >> 10;
    const int g  = lane >> 2, tg = lane & 3;
    const int R = rblk * 16, C = cch * 8;
    float4 v;
    v.x = tf32r(W[(R + g    ) * CD + C + tg    ]);
    v.y = tf32r(W[(R + g + 8) * CD + C + tg    ]);
    v.z = tf32r(W[(R + g    ) * CD + C + tg + 4]);
    v.w = tf32r(W[(R + g + 8) * CD + C + tg + 4]);
    reinterpret_cast<float4*>(g_wt)[i] = v;
}

// ---- pre-pass: agg = 3-tap stencil over joints, tf32-rounded fp32 (padded rows)
__global__ void prep_agg(const float* __restrict__ x, const float* __restrict__ A) {
    const int i  = blockIdx.x * 256 + threadIdx.x;  // 15,360,000 float4s exactly
    const int nc = i / 1875;                        // (n,c) row
    const int t4 = (i - nc * 1875) * 4;             // never crosses a w boundary
    const int w  = t4 / TD;
    const float* ps = x + (size_t)nc * NF + t4;
    const float a_s = A[w * VJ + w];
    float4 v = *reinterpret_cast<const float4*>(ps);
    float4 r;
    r.x = a_s * v.x; r.y = a_s * v.y; r.z = a_s * v.z; r.w = a_s * v.w;
    if (w > 0) {
        const float a_p = A[(w - 1) * VJ + w];
        float4 vm = *reinterpret_cast<const float4*>(ps - TD);
        r.x += a_p * vm.x; r.y += a_p * vm.y; r.z += a_p * vm.z; r.w += a_p * vm.w;
    }
    if (w < VJ - 1) {
        const float a_n = A[(w + 1) * VJ + w];
        float4 vp = *reinterpret_cast<const float4*>(ps + TD);
        r.x += a_n * vp.x; r.y += a_n * vp.y; r.z += a_n * vp.z; r.w += a_n * vp.w;
    }
    float4 o = make_float4(tf32r(r.x), tf32r(r.y), tf32r(r.z), tf32r(r.w));
    *reinterpret_cast<float4*>(g_aggt + (size_t)nc * ASTR + t4) = o;
}

// ---- main GEMM: out[n] = W @ agg[n] (+bias), tf32 single-pass
__global__ __launch_bounds__(THREADS, 2)
void gemm_kernel(const float* __restrict__ bias, float* __restrict__ out)
{
    extern __shared__ char smem[];
    const uint32_t sb = smem_u32(smem);

    const int tid  = threadIdx.x;
    const int lane = tid & 31;
    const int wid  = tid >> 5;
    const int warp_m = wid & 1;    // 2 warps -> 64 rows each
    const int warp_n = wid >> 1;   // 4 warps -> 32 cols each

    const int nt0 = blockIdx.x * BN;
    const int m   = blockIdx.y;        // M-half
    const int n   = blockIdx.z;        // batch

    float acc[4][4][4];
    #pragma unroll
    for (int a = 0; a < 4; ++a)
        #pragma unroll
        for (int b = 0; b < 4; ++b)
            #pragma unroll
            for (int e = 0; e < 4; ++e) acc[a][b][e] = 0.0f;

    // ---- cp.async producer: A fragment blobs + B rows
    auto load_chunk = [&](int kc, int stg) {
        const uint32_t stb = sb + stg * STAGE;
        // A: 8 rblocks x 4 k8-chunks x 512B = 16 KB (fragment order, verbatim copy)
        #pragma unroll
        for (int q = 0; q < 4; ++q) {
            const int idx = tid + q * 256;            // 0..1023
            const int rl = idx >> 7;                  // 0..7
            const int cl = (idx >> 5) & 3;            // 0..3
            const int l16 = idx & 31;
            const uint32_t dst = stb + OFF_A + (uint32_t)(rl * 2048 + cl * 512 + l16 * 16);
            const size_t so = ((size_t)((8 * m + rl) * 32 + 4 * kc + cl) * 32 + l16) * 4;
            cpa16(dst, g_wt + so);
        }
        // B: 32 k-rows x 32 16B-chunks (rows padded to 132 floats)
        #pragma unroll
        for (int q = 0; q < 4; ++q) {
            const int idx = tid + q * 256;            // 0..1023
            const int k = idx >> 5, cc = idx & 31;
            const uint32_t dst = stb + OFF_B + (uint32_t)(k * (BROW * 4) + cc * 16);
            const size_t so = (size_t)(n * CD + kc * BK + k) * ASTR + nt0 + cc * 4;
            cpa16(dst, g_aggt + so);
        }
        asm volatile("cp.async.commit_group;" ::: "memory");
    };

    load_chunk(0, 0);
    load_chunk(1, 1);

    const int g  = lane >> 2;
    const int tg = lane & 3;
    const uint32_t a_frag_off = OFF_A + (uint32_t)(warp_m * 4 * 2048 + lane * 16);
    // B word address component: (tg + koff)*BROW + n0 + g  (bank = 4tg+g+n0, conflict-free)
    const uint32_t b_off0 = OFF_B + (uint32_t)((tg * BROW + warp_n * 32 + g) * 4);

    for (int kc = 0; kc < NCHUNK; ++kc) {
        if (kc + 2 < NCHUNK) {
            load_chunk(kc + 2, (kc + 2) % NSTAGE);
            asm volatile("cp.async.wait_group 2;" ::: "memory");
        } else if (kc + 1 < NCHUNK) {
            asm volatile("cp.async.wait_group 1;" ::: "memory");
        } else {
            asm volatile("cp.async.wait_group 0;" ::: "memory");
        }
        __syncthreads();

        const uint32_t stb = sb + (kc % NSTAGE) * STAGE;
        #pragma unroll
        for (int ks = 0; ks < 4; ++ks) {
            uint32_t a[4][4], b[4][2];
            #pragma unroll
            for (int mt = 0; mt < 4; ++mt)
                lds128(a[mt], stb + a_frag_off + (uint32_t)(mt * 2048 + ks * 512));
            const uint32_t bbase = stb + b_off0 + (uint32_t)(ks * 8 * BROW * 4);
            #pragma unroll
            for (int nt = 0; nt < 4; ++nt) {
                b[nt][0] = lds32(bbase + (uint32_t)(nt * 8 * 4));
                b[nt][1] = lds32(bbase + (uint32_t)((4 * BROW + nt * 8) * 4));
            }
            #pragma unroll
            for (int mt = 0; mt < 4; ++mt)
                #pragma unroll
                for (int nt = 0; nt < 4; ++nt)
                    mma_tf32(acc[mt][nt], a[mt], b[nt][0], b[nt][1]);
        }
        __syncthreads();
    }

    // ---- epilogue: c0=(g,2tg) c1=(g,2tg+1) c2=(g+8,2tg) c3=(g+8,2tg+1)
    #pragma unroll
    for (int mt = 0; mt < 4; ++mt) {
        const int o0 = m * BM + warp_m * 64 + mt * 16 + g;
        const float bv0 = bias[o0];
        const float bv1 = bias[o0 + 8];
        float* row0 = out + ((size_t)n * CD + o0    ) * NF;
        float* row1 = out + ((size_t)n * CD + o0 + 8) * NF;
        #pragma unroll
        for (int nt = 0; nt < 4; ++nt) {
            const int idx = nt0 + warp_n * 32 + nt * 8 + 2 * tg;   // even; NF even
            if (idx < NF) {
                float2 v0 = make_float2(acc[mt][nt][0] + bv0, acc[mt][nt][1] + bv0);
                float2 v1 = make_float2(acc[mt][nt][2] + bv1, acc[mt][nt][3] + bv1);
                *reinterpret_cast<float2*>(row0 + idx) = v0;
                *reinterpret_cast<float2*>(row1 + idx) = v1;
            }
        }
    }
}

} // namespace

extern "C" void kernel_launch(void* const* d_in, const int* in_sizes, int n_in,
                              void* d_out, int out_size) {
    const float* x    = (const float*)d_in[0];
    const float* A    = (const float*)d_in[1];
    const float* W    = (const float*)d_in[2];
    const float* b    = (const float*)d_in[3];
    float*       outp = (float*)d_out;

    prep_w<<<64, 256>>>(W);
    prep_agg<<<60000, 256>>>(x, A);

    cudaFuncSetAttribute(gemm_kernel,
                         cudaFuncAttributeMaxDynamicSharedMemorySize, SMEM_DYN);
    dim3 grid((NF + BN - 1) / BN, 2, NB);   // 59 x 2 x 32 = 3776 CTAs
    gemm_kernel<<<grid, THREADS, SMEM_DYN>>>(b, outp);
}

// round 14
// speedup vs baseline: 3.0627x; 1.1489x over previous
#include <cuda_runtime.h>
#include <cuda_bf16.h>
#include <cstdint>

namespace {

constexpr int VJ = 25, TD = 300, CD = 256, NB = 32;
constexpr int NF   = VJ * TD;     // 7500 flattened (w,t)
constexpr int ASTR = 7504;        // padded agg row stride (16B-aligned rows)
constexpr int BM = 128, BN = 128, BK = 32;
constexpr int NCHUNK = CD / BK;   // 8
constexpr int THREADS = 256;
constexpr int NSTAGE = 3;

// per-stage smem: A fragments (16 KB) | B rows 32 x 132 floats (16896 B)
constexpr int BROW  = 132;                    // floats per B row (128 + 4 pad)
constexpr int OFF_A = 0;
constexpr int OFF_B = 16384;
constexpr int STAGE = OFF_B + BK * BROW * 4;  // 33280
constexpr int SMEM_DYN = NSTAGE * STAGE;      // 99840

// persistent scratch (allocation-free workaround)
__device__ float g_aggt[(size_t)NB * CD * ASTR + 256];  // tf32-rounded agg
__device__ float g_wt[CD * CD];                          // W in fragment order, tf32-rounded

__device__ __forceinline__ uint32_t smem_u32(const void* p) {
    uint32_t a;
    asm("{ .reg .u64 t; cvta.to.shared.u64 t, %1; cvt.u32.u64 %0, t; }" : "=r"(a) : "l"(p));
    return a;
}
__device__ __forceinline__ float tf32r(float v) {
    float r;
    asm("cvt.rna.tf32.f32 %0, %1;" : "=f"(r) : "f"(v));
    return r;
}
__device__ __forceinline__ void cpa16(uint32_t dst, const void* src) {
    asm volatile("cp.async.cg.shared.global [%0], [%1], 16;" :: "r"(dst), "l"(src));
}
__device__ __forceinline__ void lds128(uint32_t* r, uint32_t addr) {
    asm volatile("ld.shared.v4.b32 {%0,%1,%2,%3}, [%4];"
                 : "=r"(r[0]), "=r"(r[1]), "=r"(r[2]), "=r"(r[3]) : "r"(addr));
}
__device__ __forceinline__ uint32_t lds32(uint32_t addr) {
    uint32_t r;
    asm volatile("ld.shared.b32 %0, [%1];" : "=r"(r) : "r"(addr));
    return r;
}
__device__ __forceinline__ void mma_tf32(float* c, const uint32_t* a, uint32_t b0, uint32_t b1) {
    asm volatile(
        "mma.sync.aligned.m16n8k8.row.col.f32.tf32.tf32.f32 "
        "{%0,%1,%2,%3}, {%4,%5,%6,%7}, {%8,%9}, {%0,%1,%2,%3};"
        : "+f"(c[0]), "+f"(c[1]), "+f"(c[2]), "+f"(c[3])
        : "r"(a[0]), "r"(a[1]), "r"(a[2]), "r"(a[3]), "r"(b0), "r"(b1));
}

// ---- fused pre-pass: agg stencil (blocks < 60000) + W fragment repack (blocks >= 60000)
__global__ void prep_all(const float* __restrict__ x, const float* __restrict__ A,
                         const float* __restrict__ W) {
    if (blockIdx.x >= 60000) {
        // W -> tf32-rounded, m16n8k8 A-fragment order.
        // blob index ((rblk*32 + cch)*32 + lane): 4 floats = a0..a3 of tile (rblk*16, cch*8)
        const int i    = (blockIdx.x - 60000) * 256 + threadIdx.x;  // 0..16383
        const int lane = i & 31;
        const int cch  = (i >> 5) & 31;
        const int rblk = i >> 10;
        const int g  = lane >> 2, tg = lane & 3;
        const int R = rblk * 16, C = cch * 8;
        float4 v;
        v.x = tf32r(W[(R + g    ) * CD + C + tg    ]);
        v.y = tf32r(W[(R + g + 8) * CD + C + tg    ]);
        v.z = tf32r(W[(R + g    ) * CD + C + tg + 4]);
        v.w = tf32r(W[(R + g + 8) * CD + C + tg + 4]);
        reinterpret_cast<float4*>(g_wt)[i] = v;
        return;
    }
    // agg = 3-tap stencil over joints, tf32-rounded fp32 (padded rows)
    const int i  = blockIdx.x * 256 + threadIdx.x;  // 15,360,000 float4s exactly
    const int nc = i / 1875;                        // (n,c) row
    const int t4 = (i - nc * 1875) * 4;             // never crosses a w boundary
    const int w  = t4 / TD;
    const float* ps = x + (size_t)nc * NF + t4;
    const float a_s = A[w * VJ + w];
    float4 v = *reinterpret_cast<const float4*>(ps);
    float4 r;
    r.x = a_s * v.x; r.y = a_s * v.y; r.z = a_s * v.z; r.w = a_s * v.w;
    if (w > 0) {
        const float a_p = A[(w - 1) * VJ + w];
        float4 vm = *reinterpret_cast<const float4*>(ps - TD);
        r.x += a_p * vm.x; r.y += a_p * vm.y; r.z += a_p * vm.z; r.w += a_p * vm.w;
    }
    if (w < VJ - 1) {
        const float a_n = A[(w + 1) * VJ + w];
        float4 vp = *reinterpret_cast<const float4*>(ps + TD);
        r.x += a_n * vp.x; r.y += a_n * vp.y; r.z += a_n * vp.z; r.w += a_n * vp.w;
    }
    float4 o = make_float4(tf32r(r.x), tf32r(r.y), tf32r(r.z), tf32r(r.w));
    *reinterpret_cast<float4*>(g_aggt + (size_t)nc * ASTR + t4) = o;
}

// ---- main GEMM: out[n] = W @ agg[n] (+bias), tf32 single-pass
__global__ __launch_bounds__(THREADS, 2)
void gemm_kernel(const float* __restrict__ bias, float* __restrict__ out)
{
    extern __shared__ char smem[];
    const uint32_t sb = smem_u32(smem);

    const int tid  = threadIdx.x;
    const int lane = tid & 31;
    const int wid  = tid >> 5;
    const int warp_m = wid & 1;    // 2 warps -> 64 rows each
    const int warp_n = wid >> 1;   // 4 warps -> 32 cols each

    const int nt0 = blockIdx.x * BN;
    const int m   = blockIdx.y;        // M-half
    const int n   = blockIdx.z;        // batch

    float acc[4][4][4];
    #pragma unroll
    for (int a = 0; a < 4; ++a)
        #pragma unroll
        for (int b = 0; b < 4; ++b)
            #pragma unroll
            for (int e = 0; e < 4; ++e) acc[a][b][e] = 0.0f;

    // ---- cp.async producer: A fragment blobs + B rows
    auto load_chunk = [&](int kc, int stg) {
        const uint32_t stb = sb + stg * STAGE;
        // A: 8 rblocks x 4 k8-chunks x 512B = 16 KB (fragment order, verbatim copy)
        #pragma unroll
        for (int q = 0; q < 4; ++q) {
            const int idx = tid + q * 256;            // 0..1023
            const int rl = idx >> 7;                  // 0..7
            const int cl = (idx >> 5) & 3;            // 0..3
            const int l16 = idx & 31;
            const uint32_t dst = stb + OFF_A + (uint32_t)(rl * 2048 + cl * 512 + l16 * 16);
            const size_t so = ((size_t)((8 * m + rl) * 32 + 4 * kc + cl) * 32 + l16) * 4;
            cpa16(dst, g_wt + so);
        }
        // B: 32 k-rows x 32 16B-chunks (rows padded to 132 floats)
        #pragma unroll
        for (int q = 0; q < 4; ++q) {
            const int idx = tid + q * 256;            // 0..1023
            const int k = idx >> 5, cc = idx & 31;
            const uint32_t dst = stb + OFF_B + (uint32_t)(k * (BROW * 4) + cc * 16);
            const size_t so = (size_t)(n * CD + kc * BK + k) * ASTR + nt0 + cc * 4;
            cpa16(dst, g_aggt + so);
        }
        asm volatile("cp.async.commit_group;" ::: "memory");
    };

    load_chunk(0, 0);
    load_chunk(1, 1);

    const int g  = lane >> 2;
    const int tg = lane & 3;
    const uint32_t a_frag_off = OFF_A + (uint32_t)(warp_m * 4 * 2048 + lane * 16);
    // B word address component: (tg + koff)*BROW + n0 + g  (bank = 4tg+g+n0, conflict-free)
    const uint32_t b_off0 = OFF_B + (uint32_t)((tg * BROW + warp_n * 32 + g) * 4);

    auto lds_frag = [&](uint32_t stb, int ks, uint32_t a[4][4], uint32_t b[4][2]) {
        #pragma unroll
        for (int mt = 0; mt < 4; ++mt)
            lds128(a[mt], stb + a_frag_off + (uint32_t)(mt * 2048 + ks * 512));
        const uint32_t bbase = stb + b_off0 + (uint32_t)(ks * 8 * BROW * 4);
        #pragma unroll
        for (int nt = 0; nt < 4; ++nt) {
            b[nt][0] = lds32(bbase + (uint32_t)(nt * 8 * 4));
            b[nt][1] = lds32(bbase + (uint32_t)((4 * BROW + nt * 8) * 4));
        }
    };

    for (int kc = 0; kc < NCHUNK; ++kc) {
        // At loop top, chunks kc..kc+1 are in flight (kc+2 not yet committed).
        // Need chunk kc complete -> allow exactly the newer one (1 group) pending.
        if (kc + 1 < NCHUNK) {
            asm volatile("cp.async.wait_group 1;" ::: "memory");
        } else {
            asm volatile("cp.async.wait_group 0;" ::: "memory");
        }
        // single barrier: all threads have finished compute(kc-1), so prefetch
        // into stage (kc+2)%3 (== the stage compute(kc-1) read) is race-free.
        __syncthreads();
        if (kc + 2 < NCHUNK) load_chunk(kc + 2, (kc + 2) % NSTAGE);

        const uint32_t stb = sb + (kc % NSTAGE) * STAGE;
        uint32_t a0[4][4], b0[4][2], a1[4][4], b1[4][2];
        lds_frag(stb, 0, a0, b0);
        #pragma unroll
        for (int ks = 0; ks < 4; ++ks) {
            uint32_t (*ac)[4] = (ks & 1) ? a1 : a0;
            uint32_t (*bc)[2] = (ks & 1) ? b1 : b0;
            if (ks < 3) {                    // prefetch next fragments during MMAs
                uint32_t (*an)[4] = (ks & 1) ? a0 : a1;
                uint32_t (*bn)[2] = (ks & 1) ? b0 : b1;
                lds_frag(stb, ks + 1, an, bn);
            }
            #pragma unroll
            for (int mt = 0; mt < 4; ++mt)
                #pragma unroll
                for (int nt = 0; nt < 4; ++nt)
                    mma_tf32(acc[mt][nt], ac[mt], bc[nt][0], bc[nt][1]);
        }
    }

    // ---- epilogue: c0=(g,2tg) c1=(g,2tg+1) c2=(g+8,2tg) c3=(g+8,2tg+1)
    #pragma unroll
    for (int mt = 0; mt < 4; ++mt) {
        const int o0 = m * BM + warp_m * 64 + mt * 16 + g;
        const float bv0 = bias[o0];
        const float bv1 = bias[o0 + 8];
        float* row0 = out + ((size_t)n * CD + o0    ) * NF;
        float* row1 = out + ((size_t)n * CD + o0 + 8) * NF;
        #pragma unroll
        for (int nt = 0; nt < 4; ++nt) {
            const int idx = nt0 + warp_n * 32 + nt * 8 + 2 * tg;   // even; NF even
            if (idx < NF) {
                float2 v0 = make_float2(acc[mt][nt][0] + bv0, acc[mt][nt][1] + bv0);
                float2 v1 = make_float2(acc[mt][nt][2] + bv1, acc[mt][nt][3] + bv1);
                *reinterpret_cast<float2*>(row0 + idx) = v0;
                *reinterpret_cast<float2*>(row1 + idx) = v1;
            }
        }
    }
}

} // namespace

extern "C" void kernel_launch(void* const* d_in, const int* in_sizes, int n_in,
                              void* d_out, int out_size) {
    const float* x    = (const float*)d_in[0];
    const float* A    = (const float*)d_in[1];
    const float* W    = (const float*)d_in[2];
    const float* b    = (const float*)d_in[3];
    float*       outp = (float*)d_out;

    prep_all<<<60064, 256>>>(x, A, W);

    cudaFuncSetAttribute(gemm_kernel,
                         cudaFuncAttributeMaxDynamicSharedMemorySize, SMEM_DYN);
    dim3 grid((NF + BN - 1) / BN, 2, NB);   // 59 x 2 x 32 = 3776 CTAs
    gemm_kernel<<<grid, THREADS, SMEM_DYN>>>(b, outp);
}